// round 4
// baseline (speedup 1.0000x reference)
#include <cuda_runtime.h>

#define NN 50000
#define EE 800000
#define DD 128
#define PEW 98
#define KA 226      // D + PE
#define NB 512      // concatenated output width (h1|h2 for two layers)

// ---------------- scratch (device globals; no allocation) ----------------
__device__ float  g_H[(size_t)NN * NB];      // GEMM outputs (reused for both rounds)
__device__ float  g_X0[(size_t)NN * DD];     // relu(layer1)
__device__ float  g_X1[(size_t)NN * DD];     // relu(layer2)
__device__ float  g_W1[KA * NB];             // folded first-round weights
__device__ float  g_W34[DD * NB];            // concatenated second-round weights
__device__ int    g_cnt[2][NN];
__device__ int    g_cur[2][NN];
__device__ int    g_off[2][NN + 1];
__device__ float  g_dis[2][NN];
__device__ int    g_erow[2][EE];
__device__ float2 g_ecoef[2][EE];

// ---------------- prep kernels ----------------
__global__ void k_init() {
    int i = blockIdx.x * blockDim.x + threadIdx.x;
    if (i < NN) {
        g_cnt[0][i] = 0; g_cnt[1][i] = 0;
        g_cur[0][i] = 0; g_cur[1][i] = 0;
    }
}

__global__ void k_hist(const int* __restrict__ col, int lvl) {
    int e = blockIdx.x * blockDim.x + threadIdx.x;
    if (e < EE) atomicAdd(&g_cnt[lvl][col[e]], 1);
}

__global__ void k_dis() {
    int i = blockIdx.x * blockDim.x + threadIdx.x;
    if (i < NN) {
        g_dis[0][i] = rsqrtf((float)(g_cnt[0][i] + 1));  // +1 self loop
        g_dis[1][i] = rsqrtf((float)(g_cnt[1][i] + 1));
    }
}

// single-block exclusive scan over g_cnt[lvl] -> g_off[lvl]
__global__ void k_scan(int lvl) {
    __shared__ int sh[1024];
    int t = threadIdx.x;
    const int chunk = (NN + 1023) / 1024;   // 49
    int s0 = t * chunk;
    int s1 = min(s0 + chunk, NN);
    int s = 0;
    for (int i = s0; i < s1; i++) s += g_cnt[lvl][i];
    sh[t] = s;
    __syncthreads();
    for (int d = 1; d < 1024; d <<= 1) {
        int v = (t >= d) ? sh[t - d] : 0;
        __syncthreads();
        sh[t] += v;
        __syncthreads();
    }
    int run = sh[t] - s;   // exclusive prefix
    for (int i = s0; i < s1; i++) { g_off[lvl][i] = run; run += g_cnt[lvl][i]; }
    if (t == 1023) g_off[lvl][NN] = sh[1023];
}

__global__ void k_scatter(const int* __restrict__ ei, const float* __restrict__ attr, int lvl) {
    int e = blockIdx.x * blockDim.x + threadIdx.x;
    if (e >= EE) return;
    int r = ei[e];
    int c = ei[EE + e];
    int slot = g_off[lvl][c] + atomicAdd(&g_cur[lvl][c], 1);
    float dn = g_dis[lvl][r] * g_dis[lvl][c];
    float en = fminf(rsqrtf(attr[e]), 1.0f);   // attr in (0.5,1.5) > 0 always
    g_erow[lvl][slot] = r;
    g_ecoef[lvl][slot] = make_float2(dn, en);
}

// W1[:, b*128+jj] = (nodeLin[b] @ lin[b])  for b = {l11,l21,l12,l22}
__global__ void k_wcomb(const float* __restrict__ nl1, const float* __restrict__ nl2,
                        const float* __restrict__ l11, const float* __restrict__ l21,
                        const float* __restrict__ l12, const float* __restrict__ l22) {
    int i = blockIdx.x;            // 0..225
    int b = blockIdx.y;            // 0..3
    int jj = threadIdx.x;          // 0..127
    const float* nl  = (b < 2) ? nl1 : nl2;
    const float* lin = (b == 0) ? l11 : (b == 1) ? l21 : (b == 2) ? l12 : l22;
    float s = 0.f;
    #pragma unroll 8
    for (int k = 0; k < 128; k++) s += nl[i * 128 + k] * lin[k * 128 + jj];
    g_W1[i * NB + b * 128 + jj] = s;
}

__global__ void k_w34(const float* __restrict__ l13, const float* __restrict__ l23,
                      const float* __restrict__ l14, const float* __restrict__ l24) {
    int idx = blockIdx.x * blockDim.x + threadIdx.x;
    if (idx >= DD * NB) return;
    int i = idx / NB, j = idx % NB;
    int b = j / 128, jj = j % 128;
    const float* src = (b == 0) ? l13 : (b == 1) ? l23 : (b == 2) ? l14 : l24;
    g_W34[idx] = src[i * 128 + jj];
}

// ---------------- GEMM: C[N,512] = A[N,K] @ W[K,512] ----------------
// MODE 0: A = concat(x[:,0:128], d2an[:,0:98]), K=226, W=g_W1
// MODE 1: A = 0.5*(X0 + X1),                   K=128, W=g_W34
#define BM 128
#define BN 128
#define BKK 8
#define TM 8
#define TN 8

template<int MODE, int K>
__global__ __launch_bounds__(256) void k_gemm(const float* __restrict__ pa,
                                              const float* __restrict__ pb) {
    __shared__ float As[BKK][BM];
    __shared__ float Bs[BKK][BN];
    const float* __restrict__ W = (MODE == 0) ? g_W1 : g_W34;
    float* __restrict__ C = g_H;

    int bm = blockIdx.y * BM;
    int bn = blockIdx.x * BN;
    int tid = threadIdx.x;
    int tr = tid / 16, tc = tid % 16;

    float acc[TM][TN];
    #pragma unroll
    for (int i = 0; i < TM; i++)
        #pragma unroll
        for (int j = 0; j < TN; j++) acc[i][j] = 0.f;

    // A-tile load mapping: 128 rows x 8 k, 4 scalars/thread
    int a_row = tid >> 1;
    int a_k4  = (tid & 1) * 4;
    // B-tile load mapping: 8 k x 128 cols, one float4/thread
    int b_k = tid >> 5;
    int b_c = (tid & 31) * 4;

    for (int k0 = 0; k0 < K; k0 += BKK) {
        int grow = bm + a_row;
        #pragma unroll
        for (int q = 0; q < 4; q++) {
            int k = k0 + a_k4 + q;
            float v = 0.f;
            if (grow < NN && k < K) {
                if (MODE == 0)
                    v = (k < DD) ? pa[(size_t)grow * DD + k]
                                 : pb[(size_t)grow * PEW + (k - DD)];
                else
                    v = 0.5f * (g_X0[(size_t)grow * DD + k] + g_X1[(size_t)grow * DD + k]);
            }
            As[a_k4 + q][a_row] = v;
        }
        {
            int k = k0 + b_k;
            float4 v = make_float4(0.f, 0.f, 0.f, 0.f);
            if (k < K) v = *(const float4*)&W[k * NB + bn + b_c];
            *(float4*)&Bs[b_k][b_c] = v;
        }
        __syncthreads();

        #pragma unroll
        for (int kk = 0; kk < BKK; kk++) {
            float af[TM], bf[TN];
            #pragma unroll
            for (int i = 0; i < TM; i++) af[i] = As[kk][tr * TM + i];
            #pragma unroll
            for (int j = 0; j < TN; j++) bf[j] = Bs[kk][tc * TN + j];
            #pragma unroll
            for (int i = 0; i < TM; i++)
                #pragma unroll
                for (int j = 0; j < TN; j++)
                    acc[i][j] += af[i] * bf[j];
        }
        __syncthreads();
    }

    #pragma unroll
    for (int i = 0; i < TM; i++) {
        int r = bm + tr * TM + i;
        if (r < NN) {
            #pragma unroll
            for (int j = 0; j < TN; j += 4)
                *(float4*)&C[(size_t)r * NB + bn + tc * TN + j] =
                    make_float4(acc[i][j], acc[i][j + 1], acc[i][j + 2], acc[i][j + 3]);
        }
    }
}

// ---------------- aggregation: one warp per destination node ----------------
// mode 0: g_X0 = relu(agg);  mode 1: g_X1 = relu(agg);
// mode 2: out = 0.5*relu(agg);  mode 3: out += 0.5*relu(agg)
__global__ __launch_bounds__(256) void k_agg(int lvl, int h1off, int h2off,
                                             int mode, float* __restrict__ out) {
    int gwarp = (blockIdx.x * blockDim.x + threadIdx.x) >> 5;
    int lane = threadIdx.x & 31;
    if (gwarp >= NN) return;
    int node = gwarp;

    const float* __restrict__ h1 = g_H + h1off;
    const float* __restrict__ h2 = g_H + h2off;

    float dis = g_dis[lvl][node];
    float invdeg = dis * dis;   // self-loop deg_norm; edge_norm = 1

    float4 a1 = *(const float4*)&h1[(size_t)node * NB + lane * 4];
    float4 a2 = *(const float4*)&h2[(size_t)node * NB + lane * 4];
    float4 acc;
    acc.x = invdeg * a1.x + a2.x;
    acc.y = invdeg * a1.y + a2.y;
    acc.z = invdeg * a1.z + a2.z;
    acc.w = invdeg * a1.w + a2.w;

    int s0 = g_off[lvl][node];
    int s1 = g_off[lvl][node + 1];
    for (int s = s0; s < s1; s++) {
        int r = g_erow[lvl][s];
        float2 cf = g_ecoef[lvl][s];
        float4 v1 = *(const float4*)&h1[(size_t)r * NB + lane * 4];
        float4 v2 = *(const float4*)&h2[(size_t)r * NB + lane * 4];
        acc.x += cf.x * v1.x + cf.y * v2.x;
        acc.y += cf.x * v1.y + cf.y * v2.y;
        acc.z += cf.x * v1.z + cf.y * v2.z;
        acc.w += cf.x * v1.w + cf.y * v2.w;
    }

    acc.x = fmaxf(acc.x, 0.f);
    acc.y = fmaxf(acc.y, 0.f);
    acc.z = fmaxf(acc.z, 0.f);
    acc.w = fmaxf(acc.w, 0.f);

    size_t oidx = (size_t)node * DD + lane * 4;
    if (mode == 0) {
        *(float4*)&g_X0[oidx] = acc;
    } else if (mode == 1) {
        *(float4*)&g_X1[oidx] = acc;
    } else if (mode == 2) {
        acc.x *= 0.5f; acc.y *= 0.5f; acc.z *= 0.5f; acc.w *= 0.5f;
        *(float4*)&out[oidx] = acc;
    } else {
        float4 p = *(const float4*)&out[oidx];
        p.x += 0.5f * acc.x; p.y += 0.5f * acc.y;
        p.z += 0.5f * acc.z; p.w += 0.5f * acc.w;
        *(float4*)&out[oidx] = p;
    }
}

// ---------------- launch ----------------
extern "C" void kernel_launch(void* const* d_in, const int* in_sizes, int n_in,
                              void* d_out, int out_size) {
    const float* x    = (const float*)d_in[0];
    const float* d2an = (const float*)d_in[1];
    const int*   ei0  = (const int*)d_in[2];
    const float* ea0  = (const float*)d_in[3];
    const int*   ei1  = (const int*)d_in[4];
    const float* ea1  = (const float*)d_in[5];
    const float* nl1  = (const float*)d_in[6];
    const float* nl2  = (const float*)d_in[7];
    const float* l11  = (const float*)d_in[8];
    const float* l21  = (const float*)d_in[9];
    const float* l12  = (const float*)d_in[10];
    const float* l22  = (const float*)d_in[11];
    const float* l13  = (const float*)d_in[12];
    const float* l23  = (const float*)d_in[13];
    const float* l14  = (const float*)d_in[14];
    const float* l24  = (const float*)d_in[15];
    float* out = (float*)d_out;

    // --- CSR build for both levels ---
    k_init<<<(NN + 255) / 256, 256>>>();
    k_hist<<<(EE + 255) / 256, 256>>>(ei0 + EE, 0);
    k_hist<<<(EE + 255) / 256, 256>>>(ei1 + EE, 1);
    k_dis<<<(NN + 255) / 256, 256>>>();
    k_scan<<<1, 1024>>>(0);
    k_scan<<<1, 1024>>>(1);
    k_scatter<<<(EE + 255) / 256, 256>>>(ei0, ea0, 0);
    k_scatter<<<(EE + 255) / 256, 256>>>(ei1, ea1, 1);

    // --- fold weights ---
    dim3 gw(KA, 4);
    k_wcomb<<<gw, 128>>>(nl1, nl2, l11, l21, l12, l22);
    k_w34<<<(DD * NB + 255) / 256, 256>>>(l13, l23, l14, l24);

    // --- round 1: GEMM A + aggregate layers 1,2 ---
    dim3 gg(NB / BN, (NN + BM - 1) / BM);
    k_gemm<0, KA><<<gg, 256>>>(x, d2an);

    int aggGrid = (NN * 32 + 255) / 256;
    k_agg<<<aggGrid, 256>>>(0, 0, 128, 0, nullptr);    // layer1 -> X0
    k_agg<<<aggGrid, 256>>>(1, 256, 384, 1, nullptr);  // layer2 -> X1

    // --- round 2: GEMM B (A = 0.5*(X0+X1)) + aggregate layers 3,4 ---
    k_gemm<1, DD><<<gg, 256>>>(nullptr, nullptr);
    k_agg<<<aggGrid, 256>>>(0, 0, 128, 2, out);        // out  = 0.5*relu(layer3)
    k_agg<<<aggGrid, 256>>>(1, 256, 384, 3, out);      // out += 0.5*relu(layer4)
}

// round 5
// speedup vs baseline: 1.0201x; 1.0201x over previous
#include <cuda_runtime.h>

#define NN 50000
#define EE 800000
#define DD 128
#define PEW 98
#define KA 226      // D + PE
#define NB 512      // concatenated output width (h1|h2 for two layers)

typedef unsigned long long ull;

__device__ __forceinline__ ull pk2(float lo, float hi) {
    ull r;
    asm("mov.b64 %0, {%1, %2};" : "=l"(r) : "f"(lo), "f"(hi));
    return r;
}
__device__ __forceinline__ void upk2(float& lo, float& hi, ull v) {
    asm("mov.b64 {%0, %1}, %2;" : "=f"(lo), "=f"(hi) : "l"(v));
}
__device__ __forceinline__ void fma2(ull& d, ull a, ull b) {
    asm("fma.rn.f32x2 %0, %1, %2, %0;" : "+l"(d) : "l"(a), "l"(b));
}

// ---------------- scratch (device globals; no allocation) ----------------
__device__ float  g_H[(size_t)NN * NB];      // GEMM outputs (reused for both rounds)
__device__ float  g_X0[(size_t)NN * DD];     // relu(layer1)
__device__ float  g_X1[(size_t)NN * DD];     // relu(layer2)
__device__ float  g_W1[KA * NB];             // folded first-round weights
__device__ float  g_W34[DD * NB];            // concatenated second-round weights
__device__ int    g_cnt[2][NN];
__device__ int    g_cur[2][NN];
__device__ int    g_off[2][NN + 1];
__device__ float  g_dis[2][NN];
__device__ int    g_erow[2][EE];
__device__ float2 g_ecoef[2][EE];

// ---------------- prep kernels ----------------
__global__ void k_init() {
    int i = blockIdx.x * blockDim.x + threadIdx.x;
    if (i < NN) {
        g_cnt[0][i] = 0; g_cnt[1][i] = 0;
        g_cur[0][i] = 0; g_cur[1][i] = 0;
    }
}

__global__ void k_hist(const int* __restrict__ col, int lvl) {
    int e = blockIdx.x * blockDim.x + threadIdx.x;
    if (e < EE) atomicAdd(&g_cnt[lvl][col[e]], 1);
}

__global__ void k_dis() {
    int i = blockIdx.x * blockDim.x + threadIdx.x;
    if (i < NN) {
        g_dis[0][i] = rsqrtf((float)(g_cnt[0][i] + 1));  // +1 self loop
        g_dis[1][i] = rsqrtf((float)(g_cnt[1][i] + 1));
    }
}

// single-block exclusive scan over g_cnt[lvl] -> g_off[lvl]
__global__ void k_scan(int lvl) {
    __shared__ int sh[1024];
    int t = threadIdx.x;
    const int chunk = (NN + 1023) / 1024;   // 49
    int s0 = t * chunk;
    int s1 = min(s0 + chunk, NN);
    int s = 0;
    for (int i = s0; i < s1; i++) s += g_cnt[lvl][i];
    sh[t] = s;
    __syncthreads();
    for (int d = 1; d < 1024; d <<= 1) {
        int v = (t >= d) ? sh[t - d] : 0;
        __syncthreads();
        sh[t] += v;
        __syncthreads();
    }
    int run = sh[t] - s;   // exclusive prefix
    for (int i = s0; i < s1; i++) { g_off[lvl][i] = run; run += g_cnt[lvl][i]; }
    if (t == 1023) g_off[lvl][NN] = sh[1023];
}

__global__ void k_scatter(const int* __restrict__ ei, const float* __restrict__ attr, int lvl) {
    int e = blockIdx.x * blockDim.x + threadIdx.x;
    if (e >= EE) return;
    int r = ei[e];
    int c = ei[EE + e];
    int slot = g_off[lvl][c] + atomicAdd(&g_cur[lvl][c], 1);
    float dn = g_dis[lvl][r] * g_dis[lvl][c];
    float en = fminf(rsqrtf(attr[e]), 1.0f);   // attr in (0.5,1.5) > 0 always
    g_erow[lvl][slot] = r;
    g_ecoef[lvl][slot] = make_float2(dn, en);
}

// W1[:, b*128+jj] = (nodeLin[b] @ lin[b])  for b = {l11,l21,l12,l22}
__global__ void k_wcomb(const float* __restrict__ nl1, const float* __restrict__ nl2,
                        const float* __restrict__ l11, const float* __restrict__ l21,
                        const float* __restrict__ l12, const float* __restrict__ l22) {
    int i = blockIdx.x;            // 0..225
    int b = blockIdx.y;            // 0..3
    int jj = threadIdx.x;          // 0..127
    const float* nl  = (b < 2) ? nl1 : nl2;
    const float* lin = (b == 0) ? l11 : (b == 1) ? l21 : (b == 2) ? l12 : l22;
    float s = 0.f;
    #pragma unroll 8
    for (int k = 0; k < 128; k++) s += nl[i * 128 + k] * lin[k * 128 + jj];
    g_W1[i * NB + b * 128 + jj] = s;
}

__global__ void k_w34(const float* __restrict__ l13, const float* __restrict__ l23,
                      const float* __restrict__ l14, const float* __restrict__ l24) {
    int idx = blockIdx.x * blockDim.x + threadIdx.x;
    if (idx >= DD * NB) return;
    int i = idx / NB, j = idx % NB;
    int b = j / 128, jj = j % 128;
    const float* src = (b == 0) ? l13 : (b == 1) ? l23 : (b == 2) ? l14 : l24;
    g_W34[idx] = src[i * 128 + jj];
}

// ---------------- GEMM: C[N,512] = A[N,K] @ W[K,512] ----------------
// MODE 0: A = concat(x[:,0:128], d2an[:,0:98]), K=226, W=g_W1
// MODE 1: A = 0.5*(X0 + X1),                   K=128, W=g_W34
// Inner product uses fma.rn.f32x2 (packed dual fp32 FMA, sm_100+): 2x FMA
// throughput on the fma pipe, bit-identical rounding to scalar FFMA.
#define BM 128
#define BN 128
#define BKK 8
#define TM 8
#define TN 8

template<int MODE, int K>
__global__ __launch_bounds__(256) void k_gemm(const float* __restrict__ pa,
                                              const float* __restrict__ pb) {
    __shared__ float As[BKK][BM];
    __shared__ float Bs[BKK][BN];
    const float* __restrict__ W = (MODE == 0) ? g_W1 : g_W34;
    float* __restrict__ C = g_H;

    int bm = blockIdx.y * BM;
    int bn = blockIdx.x * BN;
    int tid = threadIdx.x;
    int tr = tid / 16, tc = tid % 16;

    // packed accumulators: acc2[i][j] holds columns (2j, 2j+1) of row i
    ull acc2[TM][TN / 2];
    #pragma unroll
    for (int i = 0; i < TM; i++)
        #pragma unroll
        for (int j = 0; j < TN / 2; j++) acc2[i][j] = 0ULL;

    // A-tile load mapping: 128 rows x 8 k, 4 scalars/thread
    int a_row = tid >> 1;
    int a_k4  = (tid & 1) * 4;
    // B-tile load mapping: 8 k x 128 cols, one float4/thread
    int b_k = tid >> 5;
    int b_c = (tid & 31) * 4;

    for (int k0 = 0; k0 < K; k0 += BKK) {
        int grow = bm + a_row;
        #pragma unroll
        for (int q = 0; q < 4; q++) {
            int k = k0 + a_k4 + q;
            float v = 0.f;
            if (grow < NN && k < K) {
                if (MODE == 0)
                    v = (k < DD) ? pa[(size_t)grow * DD + k]
                                 : pb[(size_t)grow * PEW + (k - DD)];
                else
                    v = 0.5f * (g_X0[(size_t)grow * DD + k] + g_X1[(size_t)grow * DD + k]);
            }
            As[a_k4 + q][a_row] = v;
        }
        {
            int k = k0 + b_k;
            float4 v = make_float4(0.f, 0.f, 0.f, 0.f);
            if (k < K) v = *(const float4*)&W[k * NB + bn + b_c];
            *(float4*)&Bs[b_k][b_c] = v;
        }
        __syncthreads();

        #pragma unroll
        for (int kk = 0; kk < BKK; kk++) {
            float4 a0 = *(const float4*)&As[kk][tr * TM];
            float4 a1 = *(const float4*)&As[kk][tr * TM + 4];
            float4 b0 = *(const float4*)&Bs[kk][tc * TN];
            float4 b1 = *(const float4*)&Bs[kk][tc * TN + 4];
            ull bb[4];
            bb[0] = pk2(b0.x, b0.y);
            bb[1] = pk2(b0.z, b0.w);
            bb[2] = pk2(b1.x, b1.y);
            bb[3] = pk2(b1.z, b1.w);
            float af[TM] = {a0.x, a0.y, a0.z, a0.w, a1.x, a1.y, a1.z, a1.w};
            #pragma unroll
            for (int i = 0; i < TM; i++) {
                ull aa = pk2(af[i], af[i]);
                #pragma unroll
                for (int j = 0; j < TN / 2; j++)
                    fma2(acc2[i][j], aa, bb[j]);
            }
        }
        __syncthreads();
    }

    #pragma unroll
    for (int i = 0; i < TM; i++) {
        int r = bm + tr * TM + i;
        if (r < NN) {
            float4 o0, o1;
            upk2(o0.x, o0.y, acc2[i][0]);
            upk2(o0.z, o0.w, acc2[i][1]);
            upk2(o1.x, o1.y, acc2[i][2]);
            upk2(o1.z, o1.w, acc2[i][3]);
            *(float4*)&C[(size_t)r * NB + bn + tc * TN]     = o0;
            *(float4*)&C[(size_t)r * NB + bn + tc * TN + 4] = o1;
        }
    }
}

// ---------------- aggregation: one warp per destination node ----------------
// mode 0: g_X0 = relu(agg);  mode 1: g_X1 = relu(agg);
// mode 2: out = 0.5*relu(agg);  mode 3: out += 0.5*relu(agg)
__global__ __launch_bounds__(256) void k_agg(int lvl, int h1off, int h2off,
                                             int mode, float* __restrict__ out) {
    int gwarp = (blockIdx.x * blockDim.x + threadIdx.x) >> 5;
    int lane = threadIdx.x & 31;
    if (gwarp >= NN) return;
    int node = gwarp;

    const float* __restrict__ h1 = g_H + h1off;
    const float* __restrict__ h2 = g_H + h2off;

    float dis = g_dis[lvl][node];
    float invdeg = dis * dis;   // self-loop deg_norm; edge_norm = 1

    float4 a1 = *(const float4*)&h1[(size_t)node * NB + lane * 4];
    float4 a2 = *(const float4*)&h2[(size_t)node * NB + lane * 4];
    float4 acc;
    acc.x = invdeg * a1.x + a2.x;
    acc.y = invdeg * a1.y + a2.y;
    acc.z = invdeg * a1.z + a2.z;
    acc.w = invdeg * a1.w + a2.w;

    int s0 = g_off[lvl][node];
    int s1 = g_off[lvl][node + 1];
    for (int s = s0; s < s1; s++) {
        int r = g_erow[lvl][s];
        float2 cf = g_ecoef[lvl][s];
        float4 v1 = *(const float4*)&h1[(size_t)r * NB + lane * 4];
        float4 v2 = *(const float4*)&h2[(size_t)r * NB + lane * 4];
        acc.x += cf.x * v1.x + cf.y * v2.x;
        acc.y += cf.x * v1.y + cf.y * v2.y;
        acc.z += cf.x * v1.z + cf.y * v2.z;
        acc.w += cf.x * v1.w + cf.y * v2.w;
    }

    acc.x = fmaxf(acc.x, 0.f);
    acc.y = fmaxf(acc.y, 0.f);
    acc.z = fmaxf(acc.z, 0.f);
    acc.w = fmaxf(acc.w, 0.f);

    size_t oidx = (size_t)node * DD + lane * 4;
    if (mode == 0) {
        *(float4*)&g_X0[oidx] = acc;
    } else if (mode == 1) {
        *(float4*)&g_X1[oidx] = acc;
    } else if (mode == 2) {
        acc.x *= 0.5f; acc.y *= 0.5f; acc.z *= 0.5f; acc.w *= 0.5f;
        *(float4*)&out[oidx] = acc;
    } else {
        float4 p = *(const float4*)&out[oidx];
        p.x += 0.5f * acc.x; p.y += 0.5f * acc.y;
        p.z += 0.5f * acc.z; p.w += 0.5f * acc.w;
        *(float4*)&out[oidx] = p;
    }
}

// ---------------- launch ----------------
extern "C" void kernel_launch(void* const* d_in, const int* in_sizes, int n_in,
                              void* d_out, int out_size) {
    const float* x    = (const float*)d_in[0];
    const float* d2an = (const float*)d_in[1];
    const int*   ei0  = (const int*)d_in[2];
    const float* ea0  = (const float*)d_in[3];
    const int*   ei1  = (const int*)d_in[4];
    const float* ea1  = (const float*)d_in[5];
    const float* nl1  = (const float*)d_in[6];
    const float* nl2  = (const float*)d_in[7];
    const float* l11  = (const float*)d_in[8];
    const float* l21  = (const float*)d_in[9];
    const float* l12  = (const float*)d_in[10];
    const float* l22  = (const float*)d_in[11];
    const float* l13  = (const float*)d_in[12];
    const float* l23  = (const float*)d_in[13];
    const float* l14  = (const float*)d_in[14];
    const float* l24  = (const float*)d_in[15];
    float* out = (float*)d_out;

    // --- CSR build for both levels ---
    k_init<<<(NN + 255) / 256, 256>>>();
    k_hist<<<(EE + 255) / 256, 256>>>(ei0 + EE, 0);
    k_hist<<<(EE + 255) / 256, 256>>>(ei1 + EE, 1);
    k_dis<<<(NN + 255) / 256, 256>>>();
    k_scan<<<1, 1024>>>(0);
    k_scan<<<1, 1024>>>(1);
    k_scatter<<<(EE + 255) / 256, 256>>>(ei0, ea0, 0);
    k_scatter<<<(EE + 255) / 256, 256>>>(ei1, ea1, 1);

    // --- fold weights ---
    dim3 gw(KA, 4);
    k_wcomb<<<gw, 128>>>(nl1, nl2, l11, l21, l12, l22);
    k_w34<<<(DD * NB + 255) / 256, 256>>>(l13, l23, l14, l24);

    // --- round 1: GEMM A + aggregate layers 1,2 ---
    dim3 gg(NB / BN, (NN + BM - 1) / BM);
    k_gemm<0, KA><<<gg, 256>>>(x, d2an);

    int aggGrid = (NN * 32 + 255) / 256;
    k_agg<<<aggGrid, 256>>>(0, 0, 128, 0, nullptr);    // layer1 -> X0
    k_agg<<<aggGrid, 256>>>(1, 256, 384, 1, nullptr);  // layer2 -> X1

    // --- round 2: GEMM B (A = 0.5*(X0+X1)) + aggregate layers 3,4 ---
    k_gemm<1, DD><<<gg, 256>>>(nullptr, nullptr);
    k_agg<<<aggGrid, 256>>>(0, 0, 128, 2, out);        // out  = 0.5*relu(layer3)
    k_agg<<<aggGrid, 256>>>(1, 256, 384, 3, out);      // out += 0.5*relu(layer4)
}